// round 12
// baseline (speedup 1.0000x reference)
#include <cuda_runtime.h>
#include <cuda_fp16.h>
#include <math_constants.h>
#include <cstdint>

// Problem constants
#define B_  64
#define D_  1500
#define T_  1000
#define DA_ 512

#define NKC 47                  // K chunks of 32 d (47*32 = 1504 >= 1500)
#define NNC 2                   // N chunks of 256 a
#define XS_PITCH 132            // fp32 words per staged x row (conflict-free)
#define XSTAGE_B (32 * XS_PITCH * 4)      // 16896
#define BSTAGE_B 16384          // 256a x 32k fp16, fragment-major
#define FRAG_B   8192           // 128t x 32k fp16, fragment-major
#define OFF_BW   0
#define OFF_RED  2048
#define OFF_FRAG 4096                       // 2 x 8192
#define OFF_X    (OFF_FRAG + 2 * FRAG_B)    // 20480, 4 stages
#define OFF_BST  (OFF_X + 4 * XSTAGE_B)     // 88064, 4 stages
#define SMEM_TOTAL (OFF_BST + 4 * BSTAGE_B) // 153600

// ===========================================================================
// Scratch (__device__ globals)
// ===========================================================================
__device__ unsigned char g_wp[NNC][NKC][BSTAGE_B];   // w1^T tiles, fragment-major fp16
__device__ float g_scores[NNC][B_][1024];            // per-nc partial scores

// ===========================================================================
// Helpers
// ===========================================================================
__device__ __forceinline__ uint32_t smem_u32(const void* p) {
    uint32_t a;
    asm("{ .reg .u64 t; cvta.to.shared.u64 t, %1; cvt.u32.u64 %0, t; }" : "=r"(a) : "l"(p));
    return a;
}
__device__ __forceinline__ void cpa16(uint32_t dst, const void* src) {
    asm volatile("cp.async.cg.shared.global [%0], [%1], 16;" :: "r"(dst), "l"(src));
}
__device__ __forceinline__ void cpa16z(uint32_t dst, const void* src, uint32_t sz) {
    asm volatile("cp.async.cg.shared.global [%0], [%1], 16, %2;" :: "r"(dst), "l"(src), "r"(sz));
}
#define CP_COMMIT() asm volatile("cp.async.commit_group;" ::: "memory")

__device__ __forceinline__ uint32_t packh2(float lo, float hi) {
    __half2 h = __floats2half2_rn(lo, hi);
    return *(uint32_t*)&h;
}

__device__ __forceinline__ void mma_f16(float c[4], const uint4& a,
                                        uint32_t b0, uint32_t b1) {
    asm volatile(
        "mma.sync.aligned.m16n8k16.row.col.f32.f16.f16.f32 "
        "{%0,%1,%2,%3}, {%4,%5,%6,%7}, {%8,%9}, {%0,%1,%2,%3};"
        : "+f"(c[0]), "+f"(c[1]), "+f"(c[2]), "+f"(c[3])
        : "r"(a.x), "r"(a.y), "r"(a.z), "r"(a.w), "r"(b0), "r"(b1));
}

// ===========================================================================
// Prep w1: [d][a] fp32 -> fragment-major fp16 B tiles (per nc: 256 a)
// ===========================================================================
__global__ __launch_bounds__(256)
void k_prep_w(const float* __restrict__ w1)
{
    __shared__ float st[32][260];
    const int nc = blockIdx.x, kc = blockIdx.y;
    const int tid = threadIdx.x;

#pragma unroll
    for (int i = 0; i < 8; i++) {
        const int idx = tid + i * 256;
        const int row = idx >> 6;               // 0..31 (d within chunk)
        const int col = (idx & 63) * 4;         // 0..252
        const int d   = kc * 32 + row;
        float4 v = make_float4(0.f, 0.f, 0.f, 0.f);
        if (d < D_) v = *(const float4*)(w1 + (size_t)d * DA_ + nc * 256 + col);
        *(float4*)&st[row][col] = v;
    }
    __syncthreads();
#pragma unroll
    for (int i = 0; i < 8; i++) {
        const int e   = tid + i * 256;
        const int nb  = e >> 6, rem = e & 63;
        const int kt  = rem >> 5, ln = rem & 31;
        const int gid = ln >> 2, tig = ln & 3;
        const int nl  = nb * 8 + gid;
        const int kl  = kt * 16 + 2 * tig;
        uint2 w;
        w.x = packh2(st[kl][nl],     st[kl + 1][nl]);
        w.y = packh2(st[kl + 8][nl], st[kl + 9][nl]);
        *(uint2*)(g_wp[nc][kc] + e * 8) = w;
    }
}

// ===========================================================================
// k_score_mma: CTA = (b, 128-t tile, nc). 8 warps (2M x 4N), warp tile 64x64.
// Fused x->fp16: raw fp32 x chunk cp.async'd into 4-stage buffer; cooperative
// transpose+convert phase fills a double-buffered fragment-major fp16 tile;
// MMA reads fragments via LDS.128. B tiles from prep_w. 1 barrier/chunk.
// ===========================================================================
__global__ __launch_bounds__(256)
void k_score_mma(const float* __restrict__ x,
                 const float* __restrict__ b1, const float* __restrict__ w2)
{
    extern __shared__ __align__(16) unsigned char smem[];
    float2* bw  = (float2*)(smem + OFF_BW);      // [256] this nc's (b1, w2)
    float*  red = (float*)(smem + OFF_RED);      // [4][128]

    const int tid  = threadIdx.x;
    const int wid  = tid >> 5, lane = tid & 31;
    const int gid  = lane >> 2, tig = lane & 3;
    const int mw   = wid >> 2;                   // 0..1  (M half, 64 t each)
    const int nw   = wid & 3;                    // 0..3  (N quarter, 64 a each)
    const int tt   = blockIdx.x, nc = blockIdx.y, b = blockIdx.z;
    const float* xb = x + (size_t)b * D_ * T_;

    bw[tid & 255] = make_float2(b1[nc * 256 + (tid & 255)], w2[nc * 256 + (tid & 255)]);

    const unsigned char* wsrc = g_wp[nc][0];

    float c[4][8][4];
#pragma unroll
    for (int mt = 0; mt < 4; mt++)
#pragma unroll
        for (int nt = 0; nt < 8; nt++)
#pragma unroll
            for (int k = 0; k < 4; k++) c[mt][nt][k] = 0.f;

    // issue chunk kc: x fp32 tile (zero-filled tails) + B fp16 tile, 1 group
    auto issue = [&](int kc) {
        unsigned char* xdst = smem + OFF_X + (size_t)(kc & 3) * XSTAGE_B;
#pragma unroll
        for (int i = 0; i < 4; i++) {           // 1024 16B chunks
            const int g   = tid + i * 256;
            const int row = g >> 5, ch = g & 31;
            const int d   = kc * 32 + row;
            const int t   = tt * 128 + ch * 4;
            const bool ok = (d < D_) && (t + 3 < T_);
            const float* src = ok ? (xb + (size_t)d * T_ + t) : xb;
            cpa16z(smem_u32(xdst + row * (XS_PITCH * 4) + ch * 16), src, ok ? 16u : 0u);
        }
        const unsigned char* Bsrc = wsrc + (size_t)kc * BSTAGE_B;
        unsigned char* bdst = smem + OFF_BST + (size_t)(kc & 3) * BSTAGE_B;
#pragma unroll
        for (int i = 0; i < 4; i++) {           // 1024 16B chunks
            const int g = tid + i * 256;
            cpa16(smem_u32(bdst + g * 16), Bsrc + g * 16);
        }
    };

    // cooperative convert: x fp32 stage[kc&3] -> fragment-major fp16 frag[kc&1]
    auto convert = [&](int kc) {
        const float* stf = (const float*)(smem + OFF_X + (size_t)(kc & 3) * XSTAGE_B);
        unsigned char* fdst = smem + OFF_FRAG + (size_t)(kc & 1) * FRAG_B;
#pragma unroll
        for (int i = 0; i < 2; i++) {
            const int e   = tid + i * 256;
            const int mb  = e >> 6, rem = e & 63;
            const int kt  = rem >> 5, ln = rem & 31;
            const int g2  = ln >> 2, t2 = ln & 3;
            const int tl  = mb * 16 + g2;
            const int kl  = kt * 16 + 2 * t2;
            uint4 w;
            w.x = packh2(stf[kl * XS_PITCH + tl],           stf[(kl + 1) * XS_PITCH + tl]);
            w.y = packh2(stf[kl * XS_PITCH + tl + 8],       stf[(kl + 1) * XS_PITCH + tl + 8]);
            w.z = packh2(stf[(kl + 8) * XS_PITCH + tl],     stf[(kl + 9) * XS_PITCH + tl]);
            w.w = packh2(stf[(kl + 8) * XS_PITCH + tl + 8], stf[(kl + 9) * XS_PITCH + tl + 8]);
            *(uint4*)(fdst + e * 16) = w;
        }
    };

    issue(0); CP_COMMIT();
    issue(1); CP_COMMIT();
    issue(2); CP_COMMIT();
    asm volatile("cp.async.wait_group 2;" ::: "memory");   // chunk 0 ready
    __syncthreads();
    convert(0);
    __syncthreads();

    for (int kc = 0; kc < NKC; kc++) {
        // MMA on chunk kc (frag[kc&1] + bstage[kc&3])
        const unsigned char* At = smem + OFF_FRAG + (size_t)(kc & 1) * FRAG_B;
        const unsigned char* Bt = smem + OFF_BST + (size_t)(kc & 3) * BSTAGE_B;
#pragma unroll
        for (int kt = 0; kt < 2; kt++) {
            uint4 af[4];
#pragma unroll
            for (int mt = 0; mt < 4; mt++)
                af[mt] = *(const uint4*)(At + ((((mw * 4 + mt) * 2 + kt) * 32 + lane) << 4));
#pragma unroll
            for (int nt = 0; nt < 8; nt++) {
                const uint2 bf = *(const uint2*)(Bt + ((((nw * 8 + nt) * 2 + kt) * 32 + lane) << 3));
#pragma unroll
                for (int mt = 0; mt < 4; mt++)
                    mma_f16(c[mt][nt], af[mt], bf.x, bf.y);
            }
        }

        if (kc + 3 < NKC) { issue(kc + 3); CP_COMMIT(); }

        if (kc + 1 < NKC) {
            // ensure chunk kc+1's cp.async group completed
            if (kc + 3 < NKC) asm volatile("cp.async.wait_group 2;" ::: "memory");
            else              asm volatile("cp.async.wait_group 0;" ::: "memory");
            convert(kc + 1);
        }
        __syncthreads();   // conv(kc+1) visible to all; frag[kc&1] free for conv(kc+2)
    }

    // Epilogue: relu(c + b1)*w2 -> per-thread partial score over this nc's a's
    float s[4][2];
#pragma unroll
    for (int mt = 0; mt < 4; mt++) { s[mt][0] = 0.f; s[mt][1] = 0.f; }
#pragma unroll
    for (int mt = 0; mt < 4; mt++)
#pragma unroll
        for (int nt = 0; nt < 8; nt++) {
            const int a = nw * 64 + nt * 8 + 2 * tig;
            const float2 q0 = bw[a], q1 = bw[a + 1];
            const float h0 = fmaxf(c[mt][nt][0] + q0.x, 0.f);
            const float h1 = fmaxf(c[mt][nt][1] + q1.x, 0.f);
            const float h2 = fmaxf(c[mt][nt][2] + q0.x, 0.f);
            const float h3 = fmaxf(c[mt][nt][3] + q1.x, 0.f);
            s[mt][0] = fmaf(h0, q0.y, fmaf(h1, q1.y, s[mt][0]));
            s[mt][1] = fmaf(h2, q0.y, fmaf(h3, q1.y, s[mt][1]));
        }

    // reduce: over tig lanes (shfl), then over the 4 N-warps (smem)
#pragma unroll
    for (int mt = 0; mt < 4; mt++)
#pragma unroll
        for (int r = 0; r < 2; r++) {
            float v = s[mt][r];
            v += __shfl_xor_sync(0xffffffffu, v, 1);
            v += __shfl_xor_sync(0xffffffffu, v, 2);
            if (tig == 0)
                red[nw * 128 + mw * 64 + mt * 16 + r * 8 + gid] = v;
        }
    __syncthreads();
    if (tid < 128) {
        const float sc = red[tid] + red[128 + tid] + red[256 + tid] + red[384 + tid];
        const int t = tt * 128 + tid;
        if (t < T_) g_scores[nc][b][t] = sc;
    }
}

// ===========================================================================
// Softmax over T per batch (sums the 2 nc partial scores -- deterministic)
// ===========================================================================
__device__ __forceinline__ float warpMax(float v) {
#pragma unroll
    for (int o = 16; o; o >>= 1) v = fmaxf(v, __shfl_xor_sync(0xffffffffu, v, o));
    return v;
}
__device__ __forceinline__ float warpSum(float v) {
#pragma unroll
    for (int o = 16; o; o >>= 1) v += __shfl_xor_sync(0xffffffffu, v, o);
    return v;
}

__global__ void k_softmax(float* __restrict__ Aout)
{
    const int b = blockIdx.x;
    const int tid = threadIdx.x;
    const int lane = tid & 31, wid = tid >> 5;
    __shared__ float sm[32];
    __shared__ float bcast;

    const bool valid = tid < T_;
    float sc = valid ? (g_scores[0][b][tid] + g_scores[1][b][tid]) : 0.f;

    float v = valid ? sc : -CUDART_INF_F;
    v = warpMax(v);
    if (lane == 0) sm[wid] = v;
    __syncthreads();
    if (wid == 0) {
        float w = sm[lane];
        w = warpMax(w);
        if (lane == 0) bcast = w;
    }
    __syncthreads();
    const float m = bcast;

    float e = valid ? expf(sc - m) : 0.f;
    float ss = warpSum(e);
    if (lane == 0) sm[wid] = ss;
    __syncthreads();
    if (wid == 0) {
        float w = sm[lane];
        w = warpSum(w);
        if (lane == 0) bcast = w;
    }
    __syncthreads();

    if (valid) Aout[(size_t)b * T_ + tid] = e / bcast;
}

// ===========================================================================
// Weighted stats
// ===========================================================================
__global__ __launch_bounds__(256)
void k_stats(const float* __restrict__ x, const float* __restrict__ Ain,
             float* __restrict__ out)
{
    __shared__ __align__(16) float sA[1000];
    const int b  = blockIdx.y;
    const int d0 = blockIdx.x * 8;

    for (int i = threadIdx.x; i < T_; i += blockDim.x) sA[i] = Ain[(size_t)b * T_ + i];
    __syncthreads();

    const int w = threadIdx.x >> 5, lane = threadIdx.x & 31;
    const int d = d0 + w;
    if (d >= D_) return;

    const float* row = x + ((size_t)b * D_ + d) * T_;
    float e = 0.f, q = 0.f;
#pragma unroll
    for (int j = 0; j < 8; j++) {
        int idx = j * 128 + lane * 4;
        if (idx < T_) {
            float4 xv = *reinterpret_cast<const float4*>(row + idx);
            float4 av = *reinterpret_cast<const float4*>(&sA[idx]);
            e = fmaf(xv.x, av.x, e); q = fmaf(xv.x * xv.x, av.x, q);
            e = fmaf(xv.y, av.y, e); q = fmaf(xv.y * xv.y, av.y, q);
            e = fmaf(xv.z, av.z, e); q = fmaf(xv.z * xv.z, av.z, q);
            e = fmaf(xv.w, av.w, e); q = fmaf(xv.w * xv.w, av.w, q);
        }
    }
    e = warpSum(e);
    q = warpSum(q);
    if (lane == 0) {
        float var = q - e * e;
        var = var > 0.f ? var : 0.f;
        out[(size_t)b * 3000 + d]        = e;
        out[(size_t)b * 3000 + 1500 + d] = sqrtf(var + 1e-5f);
    }
}

// ===========================================================================
// Launcher
// ===========================================================================
extern "C" void kernel_launch(void* const* d_in, const int* in_sizes, int n_in,
                              void* d_out, int out_size)
{
    const float* x  = (const float*)d_in[0];
    const float* w1 = (const float*)d_in[1];
    const float* b1 = (const float*)d_in[2];
    const float* w2 = (const float*)d_in[3];
    // d_in[4] = bias_2: softmax-invariant, does not affect A or layer_out.

    float* A_out = (float*)d_out;            // [64, 1000]
    float* L_out = (float*)d_out + B_ * T_;  // [64, 3000]

    cudaFuncSetAttribute(k_score_mma, cudaFuncAttributeMaxDynamicSharedMemorySize, SMEM_TOTAL);

    dim3 gw(NNC, NKC);
    k_prep_w<<<gw, 256>>>(w1);

    dim3 gs(8, NNC, B_);
    k_score_mma<<<gs, 256, SMEM_TOTAL>>>(x, b1, w2);

    k_softmax<<<B_, 1024>>>(A_out);

    dim3 g3((D_ + 7) / 8, B_);
    k_stats<<<g3, 256>>>(x, A_out, L_out);
}

// round 14
// speedup vs baseline: 1.0279x; 1.0279x over previous
#include <cuda_runtime.h>
#include <cuda_fp16.h>
#include <math_constants.h>
#include <cstdint>

// Problem constants
#define B_  64
#define D_  1500
#define T_  1000
#define DA_ 512

#define NKC 47                  // K chunks of 32 d (47*32 = 1504 >= 1500)
#define NNC 2                   // N chunks of 256 a
#define A_TILE 8192             // 128t x 32k fp16, fragment-major
#define B_TILE 16384            // 256a x 32k fp16, fragment-major
#define STAGE  (A_TILE + B_TILE)          // 24576
#define OFF_RED 4096
#define OFF_BUF 6144
#define SMEM_TOTAL (OFF_BUF + 4 * STAGE)  // 104448

#define XS_PITCH 132            // fp32 words per staged x row in prep_x

// ===========================================================================
// Scratch (__device__ globals)
// ===========================================================================
__device__ unsigned char g_xp[B_][8][NKC][A_TILE];   // x^T tiles, fragment-major fp16
__device__ unsigned char g_wp[NNC][NKC][B_TILE];     // w1^T tiles, fragment-major fp16
__device__ float g_scores[NNC][B_][1024];            // per-nc partial scores

// ===========================================================================
// Helpers
// ===========================================================================
__device__ __forceinline__ uint32_t smem_u32(const void* p) {
    uint32_t a;
    asm("{ .reg .u64 t; cvta.to.shared.u64 t, %1; cvt.u32.u64 %0, t; }" : "=r"(a) : "l"(p));
    return a;
}
__device__ __forceinline__ void cpa16(uint32_t dst, const void* src) {
    asm volatile("cp.async.cg.shared.global [%0], [%1], 16;" :: "r"(dst), "l"(src));
}
__device__ __forceinline__ void cpa16z(uint32_t dst, const void* src, uint32_t sz) {
    asm volatile("cp.async.cg.shared.global [%0], [%1], 16, %2;" :: "r"(dst), "l"(src), "r"(sz));
}
#define CP_COMMIT() asm volatile("cp.async.commit_group;" ::: "memory")

__device__ __forceinline__ uint32_t packh2(float lo, float hi) {
    __half2 h = __floats2half2_rn(lo, hi);
    return *(uint32_t*)&h;
}
__device__ __forceinline__ float4 ldcs4(const float* p) {
    float4 v;
    asm volatile("ld.global.cs.v4.f32 {%0,%1,%2,%3}, [%4];"
                 : "=f"(v.x), "=f"(v.y), "=f"(v.z), "=f"(v.w) : "l"(p));
    return v;
}

__device__ __forceinline__ void mma_f16(float c[4], const uint4& a,
                                        uint32_t b0, uint32_t b1) {
    asm volatile(
        "mma.sync.aligned.m16n8k16.row.col.f32.f16.f16.f32 "
        "{%0,%1,%2,%3}, {%4,%5,%6,%7}, {%8,%9}, {%0,%1,%2,%3};"
        : "+f"(c[0]), "+f"(c[1]), "+f"(c[2]), "+f"(c[3])
        : "r"(a.x), "r"(a.y), "r"(a.z), "r"(a.w), "r"(b0), "r"(b1));
}

// ===========================================================================
// Prep x: [b][d][t] fp32 -> fragment-major fp16 A tiles.
// Each block: (tt, kc-group of 4, b); double-buffered cp.async staging so
// the chunk j+1 load overlaps the chunk j transpose/convert/store.
// ===========================================================================
__global__ __launch_bounds__(256)
void k_prep_x(const float* __restrict__ x)
{
    __shared__ __align__(16) float st[2][32 * XS_PITCH];
    const int tt = blockIdx.x, kcg = blockIdx.y, b = blockIdx.z;
    const int tid = threadIdx.x;
    const float* xb = x + (size_t)b * D_ * T_;
    const int kc0 = kcg * 4;
    const int nj  = (kc0 + 4 <= NKC) ? 4 : (NKC - kc0);

    auto issue = [&](int j) {
        const int kc = kc0 + j;
        uint32_t dst = smem_u32(&st[j & 1][0]);
#pragma unroll
        for (int i = 0; i < 4; i++) {
            const int g   = tid + i * 256;
            const int row = g >> 5, ch = g & 31;
            const int d   = kc * 32 + row;
            const int t   = tt * 128 + ch * 4;
            const bool ok = (d < D_) && (t < T_);
            const float* src = ok ? (xb + (size_t)d * T_ + t) : xb;
            cpa16z(dst + row * (XS_PITCH * 4) + ch * 16, src, ok ? 16u : 0u);
        }
    };

    issue(0); CP_COMMIT();
    for (int j = 0; j < nj; j++) {
        const bool more = (j + 1 < nj);
        if (more) { issue(j + 1); CP_COMMIT(); }
        if (more) asm volatile("cp.async.wait_group 1;" ::: "memory");
        else      asm volatile("cp.async.wait_group 0;" ::: "memory");
        __syncthreads();
        const float* stf = &st[j & 1][0];
        const int kc = kc0 + j;
#pragma unroll
        for (int i = 0; i < 2; i++) {
            const int e   = tid + i * 256;
            const int mb  = e >> 6, rem = e & 63;
            const int kt  = rem >> 5, ln = rem & 31;
            const int g2  = ln >> 2, t2 = ln & 3;
            const int tl  = mb * 16 + g2;
            const int kl  = kt * 16 + 2 * t2;
            uint4 w;
            w.x = packh2(stf[kl * XS_PITCH + tl],           stf[(kl + 1) * XS_PITCH + tl]);
            w.y = packh2(stf[kl * XS_PITCH + tl + 8],       stf[(kl + 1) * XS_PITCH + tl + 8]);
            w.z = packh2(stf[(kl + 8) * XS_PITCH + tl],     stf[(kl + 9) * XS_PITCH + tl]);
            w.w = packh2(stf[(kl + 8) * XS_PITCH + tl + 8], stf[(kl + 9) * XS_PITCH + tl + 8]);
            *(uint4*)(g_xp[b][tt][kc] + e * 16) = w;
        }
        __syncthreads();   // stage (j&1) fully read before issue(j+2) overwrites
    }
}

// ===========================================================================
// Prep w1: [d][a] fp32 -> fragment-major fp16 B tiles (per nc: 256 a)
// ===========================================================================
__global__ __launch_bounds__(256)
void k_prep_w(const float* __restrict__ w1)
{
    __shared__ float st[32][260];
    const int nc = blockIdx.x, kc = blockIdx.y;
    const int tid = threadIdx.x;

#pragma unroll
    for (int i = 0; i < 8; i++) {
        const int idx = tid + i * 256;
        const int row = idx >> 6;               // 0..31 (d within chunk)
        const int col = (idx & 63) * 4;         // 0..252
        const int d   = kc * 32 + row;
        float4 v = make_float4(0.f, 0.f, 0.f, 0.f);
        if (d < D_) v = *(const float4*)(w1 + (size_t)d * DA_ + nc * 256 + col);
        *(float4*)&st[row][col] = v;
    }
    __syncthreads();
#pragma unroll
    for (int i = 0; i < 8; i++) {
        const int e   = tid + i * 256;
        const int nb  = e >> 6, rem = e & 63;
        const int kt  = rem >> 5, ln = rem & 31;
        const int gid = ln >> 2, tig = ln & 3;
        const int nl  = nb * 8 + gid;
        const int kl  = kt * 16 + 2 * tig;
        uint2 w;
        w.x = packh2(st[kl][nl],     st[kl + 1][nl]);
        w.y = packh2(st[kl + 8][nl], st[kl + 9][nl]);
        *(uint2*)(g_wp[nc][kc] + e * 8) = w;
    }
}

// ===========================================================================
// k_score_mma: CTA = (b, 128-t tile, nc). 8 warps (2M x 4N), warp tile 64x64,
// 4-stage cp.async pipeline, fragment-major smem, fp16 MMA. (R10 structure.)
// ===========================================================================
__global__ __launch_bounds__(256)
void k_score_mma(const float* __restrict__ b1, const float* __restrict__ w2)
{
    extern __shared__ __align__(16) unsigned char smem[];
    float2* bw  = (float2*)smem;                 // [256] this nc's (b1, w2)
    float*  red = (float*)(smem + OFF_RED);      // [4][128]
    unsigned char* bufs = smem + OFF_BUF;        // 4-stage

    const int tid  = threadIdx.x;
    const int wid  = tid >> 5, lane = tid & 31;
    const int gid  = lane >> 2, tig = lane & 3;
    const int mw   = wid >> 2;                   // 0..1  (M half, 64 t each)
    const int nw   = wid & 3;                    // 0..3  (N quarter, 64 a each)
    const int tt   = blockIdx.x, nc = blockIdx.y, b = blockIdx.z;

    bw[tid & 255] = make_float2(b1[nc * 256 + (tid & 255)], w2[nc * 256 + (tid & 255)]);

    const unsigned char* xsrc = g_xp[b][tt][0];
    const unsigned char* wsrc = g_wp[nc][0];

    float c[4][8][4];
#pragma unroll
    for (int mt = 0; mt < 4; mt++)
#pragma unroll
        for (int nt = 0; nt < 8; nt++)
#pragma unroll
            for (int k = 0; k < 4; k++) c[mt][nt][k] = 0.f;

    auto issue = [&](int kc) {
        const unsigned char* Asrc = xsrc + (size_t)kc * A_TILE;
        const unsigned char* Bsrc = wsrc + (size_t)kc * B_TILE;
        unsigned char* dst = bufs + (size_t)(kc & 3) * STAGE;
#pragma unroll
        for (int i = 0; i < 2; i++) {           // A: 512 16B chunks
            const int g = tid + i * 256;
            cpa16(smem_u32(dst + g * 16), Asrc + g * 16);
        }
#pragma unroll
        for (int i = 0; i < 4; i++) {           // B: 1024 16B chunks
            const int g = tid + i * 256;
            cpa16(smem_u32(dst + A_TILE + g * 16), Bsrc + g * 16);
        }
    };

    issue(0); CP_COMMIT();
    issue(1); CP_COMMIT();
    issue(2); CP_COMMIT();

    for (int kc = 0; kc < NKC; kc++) {
        if (kc <= NKC - 3)      asm volatile("cp.async.wait_group 2;" ::: "memory");
        else if (kc == NKC - 2) asm volatile("cp.async.wait_group 1;" ::: "memory");
        else                    asm volatile("cp.async.wait_group 0;" ::: "memory");
        __syncthreads();

        if (kc + 3 < NKC) { issue(kc + 3); CP_COMMIT(); }

        const unsigned char* stg = bufs + (size_t)(kc & 3) * STAGE;
        const unsigned char* At = stg;
        const unsigned char* Bt = stg + A_TILE;

#pragma unroll
        for (int kt = 0; kt < 2; kt++) {
            uint4 af[4];
#pragma unroll
            for (int mt = 0; mt < 4; mt++)
                af[mt] = *(const uint4*)(At + ((((mw * 4 + mt) * 2 + kt) * 32 + lane) << 4));
#pragma unroll
            for (int nt = 0; nt < 8; nt++) {
                const uint2 bf = *(const uint2*)(Bt + ((((nw * 8 + nt) * 2 + kt) * 32 + lane) << 3));
#pragma unroll
                for (int mt = 0; mt < 4; mt++)
                    mma_f16(c[mt][nt], af[mt], bf.x, bf.y);
            }
        }
    }

    // Epilogue: relu(c + b1)*w2 -> per-thread partial score over this nc's a's
    float s[4][2];
#pragma unroll
    for (int mt = 0; mt < 4; mt++) { s[mt][0] = 0.f; s[mt][1] = 0.f; }
#pragma unroll
    for (int mt = 0; mt < 4; mt++)
#pragma unroll
        for (int nt = 0; nt < 8; nt++) {
            const int a = nw * 64 + nt * 8 + 2 * tig;
            const float2 q0 = bw[a], q1 = bw[a + 1];
            const float h0 = fmaxf(c[mt][nt][0] + q0.x, 0.f);
            const float h1 = fmaxf(c[mt][nt][1] + q1.x, 0.f);
            const float h2 = fmaxf(c[mt][nt][2] + q0.x, 0.f);
            const float h3 = fmaxf(c[mt][nt][3] + q1.x, 0.f);
            s[mt][0] = fmaf(h0, q0.y, fmaf(h1, q1.y, s[mt][0]));
            s[mt][1] = fmaf(h2, q0.y, fmaf(h3, q1.y, s[mt][1]));
        }

    // reduce: over tig lanes (shfl), then over the 4 N-warps (smem)
#pragma unroll
    for (int mt = 0; mt < 4; mt++)
#pragma unroll
        for (int r = 0; r < 2; r++) {
            float v = s[mt][r];
            v += __shfl_xor_sync(0xffffffffu, v, 1);
            v += __shfl_xor_sync(0xffffffffu, v, 2);
            if (tig == 0)
                red[nw * 128 + mw * 64 + mt * 16 + r * 8 + gid] = v;
        }
    __syncthreads();
    if (tid < 128) {
        const float sc = red[tid] + red[128 + tid] + red[256 + tid] + red[384 + tid];
        const int t = tt * 128 + tid;
        if (t < T_) g_scores[nc][b][t] = sc;
    }
}

// ===========================================================================
// Softmax over T per batch (sums the 2 nc partial scores -- deterministic)
// ===========================================================================
__device__ __forceinline__ float warpMax(float v) {
#pragma unroll
    for (int o = 16; o; o >>= 1) v = fmaxf(v, __shfl_xor_sync(0xffffffffu, v, o));
    return v;
}
__device__ __forceinline__ float warpSum(float v) {
#pragma unroll
    for (int o = 16; o; o >>= 1) v += __shfl_xor_sync(0xffffffffu, v, o);
    return v;
}

__global__ void k_softmax(float* __restrict__ Aout)
{
    const int b = blockIdx.x;
    const int tid = threadIdx.x;
    const int lane = tid & 31, wid = tid >> 5;
    __shared__ float sm[32];
    __shared__ float bcast;

    const bool valid = tid < T_;
    float sc = valid ? (g_scores[0][b][tid] + g_scores[1][b][tid]) : 0.f;

    float v = valid ? sc : -CUDART_INF_F;
    v = warpMax(v);
    if (lane == 0) sm[wid] = v;
    __syncthreads();
    if (wid == 0) {
        float w = sm[lane];
        w = warpMax(w);
        if (lane == 0) bcast = w;
    }
    __syncthreads();
    const float m = bcast;

    float e = valid ? expf(sc - m) : 0.f;
    float ss = warpSum(e);
    if (lane == 0) sm[wid] = ss;
    __syncthreads();
    if (wid == 0) {
        float w = sm[lane];
        w = warpSum(w);
        if (lane == 0) bcast = w;
    }
    __syncthreads();

    if (valid) Aout[(size_t)b * T_ + tid] = e / bcast;
}

// ===========================================================================
// Weighted stats: 512 threads, 16 d-rows per block, streaming x via ld.cs
// ===========================================================================
__global__ __launch_bounds__(512)
void k_stats(const float* __restrict__ x, const float* __restrict__ Ain,
             float* __restrict__ out)
{
    __shared__ __align__(16) float sA[1000];
    const int b  = blockIdx.y;
    const int d0 = blockIdx.x * 16;

    for (int i = threadIdx.x; i < T_; i += blockDim.x) sA[i] = Ain[(size_t)b * T_ + i];
    __syncthreads();

    const int w = threadIdx.x >> 5, lane = threadIdx.x & 31;
    const int d = d0 + w;
    if (d >= D_) return;

    const float* row = x + ((size_t)b * D_ + d) * T_;
    float e = 0.f, q = 0.f;
#pragma unroll
    for (int j = 0; j < 8; j++) {
        int idx = j * 128 + lane * 4;
        if (idx < T_) {
            float4 xv = ldcs4(row + idx);
            float4 av = *reinterpret_cast<const float4*>(&sA[idx]);
            e = fmaf(xv.x, av.x, e); q = fmaf(xv.x * xv.x, av.x, q);
            e = fmaf(xv.y, av.y, e); q = fmaf(xv.y * xv.y, av.y, q);
            e = fmaf(xv.z, av.z, e); q = fmaf(xv.z * xv.z, av.z, q);
            e = fmaf(xv.w, av.w, e); q = fmaf(xv.w * xv.w, av.w, q);
        }
    }
    e = warpSum(e);
    q = warpSum(q);
    if (lane == 0) {
        float var = q - e * e;
        var = var > 0.f ? var : 0.f;
        out[(size_t)b * 3000 + d]        = e;
        out[(size_t)b * 3000 + 1500 + d] = sqrtf(var + 1e-5f);
    }
}

// ===========================================================================
// Launcher
// ===========================================================================
extern "C" void kernel_launch(void* const* d_in, const int* in_sizes, int n_in,
                              void* d_out, int out_size)
{
    const float* x  = (const float*)d_in[0];
    const float* w1 = (const float*)d_in[1];
    const float* b1 = (const float*)d_in[2];
    const float* w2 = (const float*)d_in[3];
    // d_in[4] = bias_2: softmax-invariant, does not affect A or layer_out.

    float* A_out = (float*)d_out;            // [64, 1000]
    float* L_out = (float*)d_out + B_ * T_;  // [64, 3000]

    cudaFuncSetAttribute(k_score_mma, cudaFuncAttributeMaxDynamicSharedMemorySize, SMEM_TOTAL);

    dim3 gw(NNC, NKC);
    k_prep_w<<<gw, 256>>>(w1);

    dim3 gx(8, 12, B_);
    k_prep_x<<<gx, 256>>>(x);

    dim3 gs(8, NNC, B_);
    k_score_mma<<<gs, 256, SMEM_TOTAL>>>(b1, w2);

    k_softmax<<<B_, 1024>>>(A_out);

    dim3 g3((D_ + 15) / 16, B_);
    k_stats<<<g3, 512>>>(x, A_out, L_out);
}

// round 15
// speedup vs baseline: 1.0685x; 1.0395x over previous
#include <cuda_runtime.h>
#include <cuda_fp16.h>
#include <math_constants.h>
#include <cstdint>

// Problem constants
#define B_  64
#define D_  1500
#define T_  1000
#define DA_ 512

#define NKC 47                  // K chunks of 32 d (47*32 = 1504 >= 1500)
#define NNC 2                   // N chunks of 256 a
#define A_TILE 8192             // 128t x 32k fp16, fragment-major
#define B_TILE 16384            // 256a x 32k fp16, fragment-major
#define STAGE  (A_TILE + B_TILE)          // 24576
#define OFF_RED 4096
#define OFF_BUF 6144
#define SMEM_TOTAL (OFF_BUF + 4 * STAGE)  // 104448

#define NG 4                    // batch groups
#define GB (B_ / NG)            // 16 batches per group

// ===========================================================================
// Scratch (__device__ globals)
// ===========================================================================
__device__ unsigned char g_xp[B_][8][NKC][A_TILE];   // x^T tiles, fragment-major fp16
__device__ unsigned char g_wp[NNC][NKC][B_TILE];     // w1^T tiles, fragment-major fp16
__device__ float g_scores[NNC][B_][1024];            // per-nc partial scores

// ===========================================================================
// Helpers
// ===========================================================================
__device__ __forceinline__ uint32_t smem_u32(const void* p) {
    uint32_t a;
    asm("{ .reg .u64 t; cvta.to.shared.u64 t, %1; cvt.u32.u64 %0, t; }" : "=r"(a) : "l"(p));
    return a;
}
__device__ __forceinline__ void cpa16(uint32_t dst, const void* src) {
    asm volatile("cp.async.cg.shared.global [%0], [%1], 16;" :: "r"(dst), "l"(src));
}
#define CP_COMMIT() asm volatile("cp.async.commit_group;" ::: "memory")

__device__ __forceinline__ uint32_t packh2(float lo, float hi) {
    __half2 h = __floats2half2_rn(lo, hi);
    return *(uint32_t*)&h;
}

__device__ __forceinline__ void mma_f16(float c[4], const uint4& a,
                                        uint32_t b0, uint32_t b1) {
    asm volatile(
        "mma.sync.aligned.m16n8k16.row.col.f32.f16.f16.f32 "
        "{%0,%1,%2,%3}, {%4,%5,%6,%7}, {%8,%9}, {%0,%1,%2,%3};"
        : "+f"(c[0]), "+f"(c[1]), "+f"(c[2]), "+f"(c[3])
        : "r"(a.x), "r"(a.y), "r"(a.z), "r"(a.w), "r"(b0), "r"(b1));
}

// ===========================================================================
// Prep x: [b][d][t] fp32 -> fragment-major fp16 A tiles. One chunk per block.
// ===========================================================================
__global__ __launch_bounds__(256)
void k_prep_x(const float* __restrict__ x, int b0)
{
    __shared__ float st[32][132];
    const int tt = blockIdx.x, kc = blockIdx.y, b = b0 + blockIdx.z;
    const int tid = threadIdx.x, wid = tid >> 5, lane = tid & 31;
    const float* xb = x + (size_t)b * D_ * T_;

#pragma unroll
    for (int i = 0; i < 4; i++) {
        const int dr = i * 8 + wid;
        const int d  = kc * 32 + dr;
        const int t  = tt * 128 + lane * 4;
        float4 v = make_float4(0.f, 0.f, 0.f, 0.f);
        if (d < D_ && t < T_) v = *(const float4*)(xb + (size_t)d * T_ + t);
        *(float4*)&st[dr][lane * 4] = v;
    }
    __syncthreads();
#pragma unroll
    for (int i = 0; i < 2; i++) {
        const int e   = tid + i * 256;
        const int mb  = e >> 6, rem = e & 63;
        const int kt  = rem >> 5, ln = rem & 31;
        const int gid = ln >> 2, tig = ln & 3;
        const int tl  = mb * 16 + gid;
        const int kl  = kt * 16 + 2 * tig;
        uint4 w;
        w.x = packh2(st[kl][tl],         st[kl + 1][tl]);
        w.y = packh2(st[kl][tl + 8],     st[kl + 1][tl + 8]);
        w.z = packh2(st[kl + 8][tl],     st[kl + 9][tl]);
        w.w = packh2(st[kl + 8][tl + 8], st[kl + 9][tl + 8]);
        *(uint4*)(g_xp[b][tt][kc] + e * 16) = w;
    }
}

// ===========================================================================
// Prep w1: [d][a] fp32 -> fragment-major fp16 B tiles (per nc: 256 a)
// ===========================================================================
__global__ __launch_bounds__(256)
void k_prep_w(const float* __restrict__ w1)
{
    __shared__ float st[32][260];
    const int nc = blockIdx.x, kc = blockIdx.y;
    const int tid = threadIdx.x;

#pragma unroll
    for (int i = 0; i < 8; i++) {
        const int idx = tid + i * 256;
        const int row = idx >> 6;               // 0..31 (d within chunk)
        const int col = (idx & 63) * 4;         // 0..252
        const int d   = kc * 32 + row;
        float4 v = make_float4(0.f, 0.f, 0.f, 0.f);
        if (d < D_) v = *(const float4*)(w1 + (size_t)d * DA_ + nc * 256 + col);
        *(float4*)&st[row][col] = v;
    }
    __syncthreads();
#pragma unroll
    for (int i = 0; i < 8; i++) {
        const int e   = tid + i * 256;
        const int nb  = e >> 6, rem = e & 63;
        const int kt  = rem >> 5, ln = rem & 31;
        const int gid = ln >> 2, tig = ln & 3;
        const int nl  = nb * 8 + gid;
        const int kl  = kt * 16 + 2 * tig;
        uint2 w;
        w.x = packh2(st[kl][nl],     st[kl + 1][nl]);
        w.y = packh2(st[kl + 8][nl], st[kl + 9][nl]);
        *(uint2*)(g_wp[nc][kc] + e * 8) = w;
    }
}

// ===========================================================================
// k_score_mma: CTA = (b, 128-t tile, nc). 8 warps (2M x 4N), warp tile 64x64,
// 4-stage cp.async pipeline, fragment-major smem, fp16 MMA.
// ===========================================================================
__global__ __launch_bounds__(256)
void k_score_mma(const float* __restrict__ b1, const float* __restrict__ w2, int b0)
{
    extern __shared__ __align__(16) unsigned char smem[];
    float2* bw  = (float2*)smem;                 // [256] this nc's (b1, w2)
    float*  red = (float*)(smem + OFF_RED);      // [4][128]
    unsigned char* bufs = smem + OFF_BUF;        // 4-stage

    const int tid  = threadIdx.x;
    const int wid  = tid >> 5, lane = tid & 31;
    const int gid  = lane >> 2, tig = lane & 3;
    const int mw   = wid >> 2;                   // 0..1  (M half, 64 t each)
    const int nw   = wid & 3;                    // 0..3  (N quarter, 64 a each)
    const int tt   = blockIdx.x, nc = blockIdx.y, b = b0 + blockIdx.z;

    bw[tid & 255] = make_float2(b1[nc * 256 + (tid & 255)], w2[nc * 256 + (tid & 255)]);

    const unsigned char* xsrc = g_xp[b][tt][0];
    const unsigned char* wsrc = g_wp[nc][0];

    float c[4][8][4];
#pragma unroll
    for (int mt = 0; mt < 4; mt++)
#pragma unroll
        for (int nt = 0; nt < 8; nt++)
#pragma unroll
            for (int k = 0; k < 4; k++) c[mt][nt][k] = 0.f;

    auto issue = [&](int kc) {
        const unsigned char* Asrc = xsrc + (size_t)kc * A_TILE;
        const unsigned char* Bsrc = wsrc + (size_t)kc * B_TILE;
        unsigned char* dst = bufs + (size_t)(kc & 3) * STAGE;
#pragma unroll
        for (int i = 0; i < 2; i++) {           // A: 512 16B chunks
            const int g = tid + i * 256;
            cpa16(smem_u32(dst + g * 16), Asrc + g * 16);
        }
#pragma unroll
        for (int i = 0; i < 4; i++) {           // B: 1024 16B chunks
            const int g = tid + i * 256;
            cpa16(smem_u32(dst + A_TILE + g * 16), Bsrc + g * 16);
        }
    };

    issue(0); CP_COMMIT();
    issue(1); CP_COMMIT();
    issue(2); CP_COMMIT();

    for (int kc = 0; kc < NKC; kc++) {
        if (kc <= NKC - 3)      asm volatile("cp.async.wait_group 2;" ::: "memory");
        else if (kc == NKC - 2) asm volatile("cp.async.wait_group 1;" ::: "memory");
        else                    asm volatile("cp.async.wait_group 0;" ::: "memory");
        __syncthreads();

        if (kc + 3 < NKC) { issue(kc + 3); CP_COMMIT(); }

        const unsigned char* stg = bufs + (size_t)(kc & 3) * STAGE;
        const unsigned char* At = stg;
        const unsigned char* Bt = stg + A_TILE;

#pragma unroll
        for (int kt = 0; kt < 2; kt++) {
            uint4 af[4];
#pragma unroll
            for (int mt = 0; mt < 4; mt++)
                af[mt] = *(const uint4*)(At + ((((mw * 4 + mt) * 2 + kt) * 32 + lane) << 4));
#pragma unroll
            for (int nt = 0; nt < 8; nt++) {
                const uint2 bf = *(const uint2*)(Bt + ((((nw * 8 + nt) * 2 + kt) * 32 + lane) << 3));
#pragma unroll
                for (int mt = 0; mt < 4; mt++)
                    mma_f16(c[mt][nt], af[mt], bf.x, bf.y);
            }
        }
    }

    // Epilogue: relu(c + b1)*w2 -> per-thread partial score over this nc's a's
    float s[4][2];
#pragma unroll
    for (int mt = 0; mt < 4; mt++) { s[mt][0] = 0.f; s[mt][1] = 0.f; }
#pragma unroll
    for (int mt = 0; mt < 4; mt++)
#pragma unroll
        for (int nt = 0; nt < 8; nt++) {
            const int a = nw * 64 + nt * 8 + 2 * tig;
            const float2 q0 = bw[a], q1 = bw[a + 1];
            const float h0 = fmaxf(c[mt][nt][0] + q0.x, 0.f);
            const float h1 = fmaxf(c[mt][nt][1] + q1.x, 0.f);
            const float h2 = fmaxf(c[mt][nt][2] + q0.x, 0.f);
            const float h3 = fmaxf(c[mt][nt][3] + q1.x, 0.f);
            s[mt][0] = fmaf(h0, q0.y, fmaf(h1, q1.y, s[mt][0]));
            s[mt][1] = fmaf(h2, q0.y, fmaf(h3, q1.y, s[mt][1]));
        }

    // reduce: over tig lanes (shfl), then over the 4 N-warps (smem)
#pragma unroll
    for (int mt = 0; mt < 4; mt++)
#pragma unroll
        for (int r = 0; r < 2; r++) {
            float v = s[mt][r];
            v += __shfl_xor_sync(0xffffffffu, v, 1);
            v += __shfl_xor_sync(0xffffffffu, v, 2);
            if (tig == 0)
                red[nw * 128 + mw * 64 + mt * 16 + r * 8 + gid] = v;
        }
    __syncthreads();
    if (tid < 128) {
        const float sc = red[tid] + red[128 + tid] + red[256 + tid] + red[384 + tid];
        const int t = tt * 128 + tid;
        if (t < T_) g_scores[nc][b][t] = sc;
    }
}

// ===========================================================================
// Softmax over T per batch (sums the 2 nc partial scores -- deterministic)
// ===========================================================================
__device__ __forceinline__ float warpMax(float v) {
#pragma unroll
    for (int o = 16; o; o >>= 1) v = fmaxf(v, __shfl_xor_sync(0xffffffffu, v, o));
    return v;
}
__device__ __forceinline__ float warpSum(float v) {
#pragma unroll
    for (int o = 16; o; o >>= 1) v += __shfl_xor_sync(0xffffffffu, v, o);
    return v;
}

__global__ void k_softmax(float* __restrict__ Aout, int b0)
{
    const int b = b0 + blockIdx.x;
    const int tid = threadIdx.x;
    const int lane = tid & 31, wid = tid >> 5;
    __shared__ float sm[32];
    __shared__ float bcast;

    const bool valid = tid < T_;
    float sc = valid ? (g_scores[0][b][tid] + g_scores[1][b][tid]) : 0.f;

    float v = valid ? sc : -CUDART_INF_F;
    v = warpMax(v);
    if (lane == 0) sm[wid] = v;
    __syncthreads();
    if (wid == 0) {
        float w = sm[lane];
        w = warpMax(w);
        if (lane == 0) bcast = w;
    }
    __syncthreads();
    const float m = bcast;

    float e = valid ? expf(sc - m) : 0.f;
    float ss = warpSum(e);
    if (lane == 0) sm[wid] = ss;
    __syncthreads();
    if (wid == 0) {
        float w = sm[lane];
        w = warpSum(w);
        if (lane == 0) bcast = w;
    }
    __syncthreads();

    if (valid) Aout[(size_t)b * T_ + tid] = e / bcast;
}

// ===========================================================================
// Weighted stats
// ===========================================================================
__global__ __launch_bounds__(256)
void k_stats(const float* __restrict__ x, const float* __restrict__ Ain,
             float* __restrict__ out, int b0)
{
    __shared__ __align__(16) float sA[1000];
    const int b  = b0 + blockIdx.y;
    const int d0 = blockIdx.x * 8;

    for (int i = threadIdx.x; i < T_; i += blockDim.x) sA[i] = Ain[(size_t)b * T_ + i];
    __syncthreads();

    const int w = threadIdx.x >> 5, lane = threadIdx.x & 31;
    const int d = d0 + w;
    if (d >= D_) return;

    const float* row = x + ((size_t)b * D_ + d) * T_;
    float e = 0.f, q = 0.f;
#pragma unroll
    for (int j = 0; j < 8; j++) {
        int idx = j * 128 + lane * 4;
        if (idx < T_) {
            float4 xv = *reinterpret_cast<const float4*>(row + idx);
            float4 av = *reinterpret_cast<const float4*>(&sA[idx]);
            e = fmaf(xv.x, av.x, e); q = fmaf(xv.x * xv.x, av.x, q);
            e = fmaf(xv.y, av.y, e); q = fmaf(xv.y * xv.y, av.y, q);
            e = fmaf(xv.z, av.z, e); q = fmaf(xv.z * xv.z, av.z, q);
            e = fmaf(xv.w, av.w, e); q = fmaf(xv.w * xv.w, av.w, q);
        }
    }
    e = warpSum(e);
    q = warpSum(q);
    if (lane == 0) {
        float var = q - e * e;
        var = var > 0.f ? var : 0.f;
        out[(size_t)b * 3000 + d]        = e;
        out[(size_t)b * 3000 + 1500 + d] = sqrtf(var + 1e-5f);
    }
}

// ===========================================================================
// Launcher: two-stream pipelined schedule (capture-fork via events)
// ===========================================================================
extern "C" void kernel_launch(void* const* d_in, const int* in_sizes, int n_in,
                              void* d_out, int out_size)
{
    const float* x  = (const float*)d_in[0];
    const float* w1 = (const float*)d_in[1];
    const float* b1 = (const float*)d_in[2];
    const float* w2 = (const float*)d_in[3];
    // d_in[4] = bias_2: softmax-invariant, does not affect A or layer_out.

    float* A_out = (float*)d_out;            // [64, 1000]
    float* L_out = (float*)d_out + B_ * T_;  // [64, 3000]

    static cudaStream_t s2;
    static cudaEvent_t evFork, evJoin, evP0, evP[NG], evK[NG];
    static bool inited = false;
    if (!inited) {
        cudaFuncSetAttribute(k_score_mma, cudaFuncAttributeMaxDynamicSharedMemorySize, SMEM_TOTAL);
        cudaStreamCreateWithFlags(&s2, cudaStreamNonBlocking);
        cudaEventCreateWithFlags(&evFork, cudaEventDisableTiming);
        cudaEventCreateWithFlags(&evJoin, cudaEventDisableTiming);
        cudaEventCreateWithFlags(&evP0,   cudaEventDisableTiming);
        for (int g = 0; g < NG; g++) {
            cudaEventCreateWithFlags(&evP[g], cudaEventDisableTiming);
            cudaEventCreateWithFlags(&evK[g], cudaEventDisableTiming);
        }
        inited = true;
    }

    cudaStream_t ms = cudaStreamPerThread;

    // fork s2 from main
    cudaEventRecord(evFork, ms);
    cudaStreamWaitEvent(s2, evFork, 0);

    // main: w prep + group-0 x prep
    dim3 gw(NNC, NKC);
    k_prep_w<<<gw, 256, 0, ms>>>(w1);
    dim3 gx(8, NKC, GB);
    k_prep_x<<<gx, 256, 0, ms>>>(x, 0);
    cudaEventRecord(evP0, ms);

    // s2: x prep for groups 1..3 (after group 0's, so it doesn't steal its DRAM)
    cudaStreamWaitEvent(s2, evP0, 0);
    for (int g = 1; g < NG; g++) {
        k_prep_x<<<gx, 256, 0, s2>>>(x, g * GB);
        cudaEventRecord(evP[g], s2);
    }

    // main: k_score per group
    dim3 gs(8, NNC, GB);
    for (int g = 0; g < NG; g++) {
        if (g > 0) cudaStreamWaitEvent(ms, evP[g], 0);
        k_score_mma<<<gs, 256, SMEM_TOTAL, ms>>>(b1, w2, g * GB);
        cudaEventRecord(evK[g], ms);
    }

    // s2: softmax + stats per group as scores arrive
    dim3 g3((D_ + 7) / 8, GB);
    for (int g = 0; g < NG; g++) {
        cudaStreamWaitEvent(s2, evK[g], 0);
        k_softmax<<<GB, 1024, 0, s2>>>(A_out, g * GB);
        k_stats<<<g3, 256, 0, s2>>>(x, A_out, L_out, g * GB);
    }

    // join
    cudaEventRecord(evJoin, s2);
    cudaStreamWaitEvent(ms, evJoin, 0);
}